// round 2
// baseline (speedup 1.0000x reference)
#include <cuda_runtime.h>
#include <math.h>

// Problem constants
#define B_SZ   4096
#define IN_SZ  4096
#define P_SZ   16
#define E_SZ   256
#define M_SZ   (B_SZ * P_SZ)      // 65536 GEMM rows
#define EPS_BN 1e-5

// ---------------------------------------------------------------------------
// Scratch (device globals; no allocation allowed in kernel_launch)
// ---------------------------------------------------------------------------
__device__ float  g_xn[B_SZ * IN_SZ];          // normalized x        (67 MB)
__device__ float  g_q [M_SZ * E_SZ];           // Q[b*16+p][e]        (67 MB)
__device__ float  g_k [M_SZ * E_SZ];           // K                   (67 MB)
__device__ float  g_v [M_SZ * E_SZ];           // V                   (67 MB)
__device__ float  g_a [IN_SZ];                 // per-col scale  = rstd*gamma
__device__ float  g_b [IN_SZ];                 // per-col shift  = beta - mean*rstd*gamma
__device__ double g_ps [8 * IN_SZ];            // partial sums
__device__ double g_ps2[8 * IN_SZ];            // partial sums of squares

// ---------------------------------------------------------------------------
// Kernel 1a: partial column sums (grid 64 x 8; block = 4 rowgroups x 64 cols)
// ---------------------------------------------------------------------------
__global__ __launch_bounds__(256) void k_stats_partial(const float* __restrict__ x)
{
    const int c  = blockIdx.x * 64 + (threadIdx.x & 63);
    const int rg = threadIdx.x >> 6;              // 0..3
    const int rbase = blockIdx.y * 512;

    double s0 = 0.0, s1 = 0.0, q0 = 0.0, q1 = 0.0;
    #pragma unroll 4
    for (int i = 0; i < 128; i += 2) {
        float v0 = x[(size_t)(rbase + rg + 4 * i)       * IN_SZ + c];
        float v1 = x[(size_t)(rbase + rg + 4 * (i + 1)) * IN_SZ + c];
        s0 += (double)v0;  q0 += (double)v0 * (double)v0;
        s1 += (double)v1;  q1 += (double)v1 * (double)v1;
    }

    __shared__ double sh [256];
    __shared__ double sh2[256];
    sh [threadIdx.x] = s0 + s1;
    sh2[threadIdx.x] = q0 + q1;
    __syncthreads();

    if (rg == 0) {
        const int t = threadIdx.x;            // 0..63
        double s  = sh [t] + sh [t + 64] + sh [t + 128] + sh [t + 192];
        double s2 = sh2[t] + sh2[t + 64] + sh2[t + 128] + sh2[t + 192];
        g_ps [blockIdx.y * IN_SZ + c] = s;
        g_ps2[blockIdx.y * IN_SZ + c] = s2;
    }
}

// ---------------------------------------------------------------------------
// Kernel 1b: finalize mean/var -> fused scale/shift per column
// ---------------------------------------------------------------------------
__global__ __launch_bounds__(256) void k_stats_final(const float* __restrict__ gamma,
                                                     const float* __restrict__ beta)
{
    const int c = blockIdx.x * 256 + threadIdx.x;
    double s = 0.0, s2 = 0.0;
    #pragma unroll
    for (int y = 0; y < 8; y++) {
        s  += g_ps [y * IN_SZ + c];
        s2 += g_ps2[y * IN_SZ + c];
    }
    const double mean = s / (double)B_SZ;
    const double var  = s2 / (double)B_SZ - mean * mean;   // biased, as BN
    const float  rstd = (float)rsqrt(var + EPS_BN);
    const float  a    = rstd * gamma[c];
    g_a[c] = a;
    g_b[c] = beta[c] - (float)mean * a;
}

// ---------------------------------------------------------------------------
// Kernel 2: normalize  xn = x*a + b   (float4 streaming)
// ---------------------------------------------------------------------------
__global__ __launch_bounds__(256) void k_normalize(const float* __restrict__ x)
{
    const int i = blockIdx.x * 256 + threadIdx.x;   // float4 index (4,194,304 total)
    const float4* x4 = (const float4*)x;
    const float4* a4 = (const float4*)g_a;
    const float4* b4 = (const float4*)g_b;
    float4* o4 = (float4*)g_xn;

    const int c4 = i & 1023;                        // column/4 (16 KB tables, L2-hot)
    float4 xv = x4[i];
    float4 av = a4[c4];
    float4 bv = b4[c4];
    float4 r;
    r.x = fmaf(xv.x, av.x, bv.x);
    r.y = fmaf(xv.y, av.y, bv.y);
    r.z = fmaf(xv.z, av.z, bv.z);
    r.w = fmaf(xv.w, av.w, bv.w);
    o4[i] = r;
}

// ---------------------------------------------------------------------------
// Kernel 3: QKV projection GEMM (fp32, 128x128x16 tiles, double-buffered smem,
//           8x8 per-thread microtile).  C[m][e] = sum_k xn[m][k] * W[e][k] + bias[e]
//           grid = (65536/128, 6): blockIdx.y -> {WQ lo/hi, WK lo/hi, WV lo/hi}
// ---------------------------------------------------------------------------
#define GBM 128
#define GBN 128
#define GBK 16
#define GPD 4

__global__ __launch_bounds__(256) void k_gemm_qkv(
    const float* __restrict__ WQ, const float* __restrict__ bQ,
    const float* __restrict__ WK, const float* __restrict__ bK,
    const float* __restrict__ WV, const float* __restrict__ bV)
{
    __shared__ __align__(16) float As[2][GBK][GBM + GPD];
    __shared__ __align__(16) float Bs[2][GBK][GBN + GPD];

    const int by  = blockIdx.y;
    const int mat = by >> 1;
    const float* W    = (mat == 0) ? WQ : (mat == 1) ? WK : WV;
    const float* bias = (mat == 0) ? bQ : (mat == 1) ? bK : bV;
    float*       C    = (mat == 0) ? g_q : (mat == 1) ? g_k : g_v;
    const int n0 = (by & 1) * GBN;          // 0 or 128 within the 256 output cols
    const int m0 = blockIdx.x * GBM;

    const int tid = threadIdx.x;
    const int lr  = tid >> 2;               // 0..63 (tile row for loads)
    const int lq  = tid & 3;                // 0..3  (k-quad for loads)

    const float* Abase = g_xn + (size_t)m0 * E_SZ + lq * 4;
    const float* Bbase = W    + (size_t)n0 * E_SZ + lq * 4;

    // load k-chunk 0 into registers
    float4 a0 = *(const float4*)(Abase + (size_t)lr        * E_SZ);
    float4 a1 = *(const float4*)(Abase + (size_t)(lr + 64) * E_SZ);
    float4 b0 = *(const float4*)(Bbase + (size_t)lr        * E_SZ);
    float4 b1 = *(const float4*)(Bbase + (size_t)(lr + 64) * E_SZ);

    // store stage 0
    {
        As[0][lq*4+0][lr]      = a0.x; As[0][lq*4+1][lr]      = a0.y;
        As[0][lq*4+2][lr]      = a0.z; As[0][lq*4+3][lr]      = a0.w;
        As[0][lq*4+0][lr+64]   = a1.x; As[0][lq*4+1][lr+64]   = a1.y;
        As[0][lq*4+2][lr+64]   = a1.z; As[0][lq*4+3][lr+64]   = a1.w;
        Bs[0][lq*4+0][lr]      = b0.x; Bs[0][lq*4+1][lr]      = b0.y;
        Bs[0][lq*4+2][lr]      = b0.z; Bs[0][lq*4+3][lr]      = b0.w;
        Bs[0][lq*4+0][lr+64]   = b1.x; Bs[0][lq*4+1][lr+64]   = b1.y;
        Bs[0][lq*4+2][lr+64]   = b1.z; Bs[0][lq*4+3][lr+64]   = b1.w;
    }
    __syncthreads();

    const int ty = tid >> 4;                 // 0..15
    const int tx = tid & 15;                 // 0..15

    float acc[8][8];
    #pragma unroll
    for (int i = 0; i < 8; i++)
        #pragma unroll
        for (int j = 0; j < 8; j++) acc[i][j] = 0.0f;

    int s = 0;
    for (int kt = 0; kt < 16; kt++) {
        if (kt < 15) {
            const int ko = (kt + 1) * 16;
            a0 = *(const float4*)(Abase + (size_t)lr        * E_SZ + ko);
            a1 = *(const float4*)(Abase + (size_t)(lr + 64) * E_SZ + ko);
            b0 = *(const float4*)(Bbase + (size_t)lr        * E_SZ + ko);
            b1 = *(const float4*)(Bbase + (size_t)(lr + 64) * E_SZ + ko);
        }
        #pragma unroll
        for (int k = 0; k < GBK; k++) {
            float4 af0 = *(const float4*)&As[s][k][ty * 4];
            float4 af1 = *(const float4*)&As[s][k][64 + ty * 4];
            float4 bf0 = *(const float4*)&Bs[s][k][tx * 4];
            float4 bf1 = *(const float4*)&Bs[s][k][64 + tx * 4];
            float av[8] = {af0.x, af0.y, af0.z, af0.w, af1.x, af1.y, af1.z, af1.w};
            float bw[8] = {bf0.x, bf0.y, bf0.z, bf0.w, bf1.x, bf1.y, bf1.z, bf1.w};
            #pragma unroll
            for (int i = 0; i < 8; i++)
                #pragma unroll
                for (int j = 0; j < 8; j++)
                    acc[i][j] = fmaf(av[i], bw[j], acc[i][j]);
        }
        if (kt < 15) {
            const int t = s ^ 1;
            As[t][lq*4+0][lr]    = a0.x; As[t][lq*4+1][lr]    = a0.y;
            As[t][lq*4+2][lr]    = a0.z; As[t][lq*4+3][lr]    = a0.w;
            As[t][lq*4+0][lr+64] = a1.x; As[t][lq*4+1][lr+64] = a1.y;
            As[t][lq*4+2][lr+64] = a1.z; As[t][lq*4+3][lr+64] = a1.w;
            Bs[t][lq*4+0][lr]    = b0.x; Bs[t][lq*4+1][lr]    = b0.y;
            Bs[t][lq*4+2][lr]    = b0.z; Bs[t][lq*4+3][lr]    = b0.w;
            Bs[t][lq*4+0][lr+64] = b1.x; Bs[t][lq*4+1][lr+64] = b1.y;
            Bs[t][lq*4+2][lr+64] = b1.z; Bs[t][lq*4+3][lr+64] = b1.w;
            __syncthreads();
            s = t;
        }
    }

    // epilogue: add bias, write float4s
    float bv[8];
    #pragma unroll
    for (int j = 0; j < 4; j++) {
        bv[j]     = bias[n0 + tx * 4 + j];
        bv[4 + j] = bias[n0 + 64 + tx * 4 + j];
    }
    #pragma unroll
    for (int i = 0; i < 8; i++) {
        const int row = m0 + ((i < 4) ? (ty * 4 + i) : (64 + ty * 4 + (i - 4)));
        float* crow = C + (size_t)row * E_SZ + n0;
        float4 o0 = {acc[i][0] + bv[0], acc[i][1] + bv[1],
                     acc[i][2] + bv[2], acc[i][3] + bv[3]};
        float4 o1 = {acc[i][4] + bv[4], acc[i][5] + bv[5],
                     acc[i][6] + bv[6], acc[i][7] + bv[7]};
        *(float4*)(crow + tx * 4)      = o0;
        *(float4*)(crow + 64 + tx * 4) = o1;
    }
}

// ---------------------------------------------------------------------------
// Kernel 4: per-batch-item attention + residual.
//   CTA = one b, thread = one e.  Single-pass softmax (logits ~N(0,0.16), no
//   max subtraction needed; mathematically identical).
//   scores[e][f] = sum_p Q[b,p,e]*K[b,p,f];  w = exp(scores/16)
//   prod[e][p]   = (sum_f w*V[b,p,f]) / (sum_f w)
//   out[b, e*16+p] = prod + x[b, e*16+p]
// ---------------------------------------------------------------------------
__global__ __launch_bounds__(256) void k_attention(const float* __restrict__ x,
                                                   float* __restrict__ out)
{
    const int b = blockIdx.x;
    const int e = threadIdx.x;

    __shared__ __align__(16) float sK[P_SZ][E_SZ];
    __shared__ __align__(16) float sV[P_SZ][E_SZ];

    const float* qb = g_q + (size_t)b * (P_SZ * E_SZ);
    const float* kb = g_k + (size_t)b * (P_SZ * E_SZ);
    const float* vb = g_v + (size_t)b * (P_SZ * E_SZ);

    float q[P_SZ];
    #pragma unroll
    for (int p = 0; p < P_SZ; p++) {
        q[p]     = qb[p * E_SZ + e];
        sK[p][e] = kb[p * E_SZ + e];
        sV[p][e] = vb[p * E_SZ + e];
    }
    __syncthreads();

    float acc[P_SZ];
    #pragma unroll
    for (int p = 0; p < P_SZ; p++) acc[p] = 0.0f;
    float ssum = 0.0f;

    for (int f = 0; f < E_SZ; f += 4) {
        float s0 = 0.f, s1 = 0.f, s2 = 0.f, s3 = 0.f;
        #pragma unroll
        for (int p = 0; p < P_SZ; p++) {
            float4 kv = *(const float4*)&sK[p][f];   // uniform -> LDS broadcast
            s0 = fmaf(q[p], kv.x, s0);
            s1 = fmaf(q[p], kv.y, s1);
            s2 = fmaf(q[p], kv.z, s2);
            s3 = fmaf(q[p], kv.w, s3);
        }
        const float w0 = __expf(s0 * 0.0625f);       // /SCALE, SCALE = 16
        const float w1 = __expf(s1 * 0.0625f);
        const float w2 = __expf(s2 * 0.0625f);
        const float w3 = __expf(s3 * 0.0625f);
        ssum += (w0 + w1) + (w2 + w3);
        #pragma unroll
        for (int p = 0; p < P_SZ; p++) {
            float4 vv = *(const float4*)&sV[p][f];
            acc[p] = fmaf(w0, vv.x, acc[p]);
            acc[p] = fmaf(w1, vv.y, acc[p]);
            acc[p] = fmaf(w2, vv.z, acc[p]);
            acc[p] = fmaf(w3, vv.w, acc[p]);
        }
    }

    const float inv = 1.0f / ssum;
    const float* xrow = x   + (size_t)b * IN_SZ + e * P_SZ;
    float*       orow = out + (size_t)b * IN_SZ + e * P_SZ;
    #pragma unroll
    for (int p4 = 0; p4 < 4; p4++) {
        float4 xv = *(const float4*)(xrow + p4 * 4);
        float4 o;
        o.x = fmaf(acc[p4 * 4 + 0], inv, xv.x);
        o.y = fmaf(acc[p4 * 4 + 1], inv, xv.y);
        o.z = fmaf(acc[p4 * 4 + 2], inv, xv.z);
        o.w = fmaf(acc[p4 * 4 + 3], inv, xv.w);
        *(float4*)(orow + p4 * 4) = o;
    }
}

// ---------------------------------------------------------------------------
// Entry point (graph-capturable: kernel launches only)
// ---------------------------------------------------------------------------
extern "C" void kernel_launch(void* const* d_in, const int* in_sizes, int n_in,
                              void* d_out, int out_size)
{
    const float* x     = (const float*)d_in[0];
    const float* gamma = (const float*)d_in[1];
    const float* beta  = (const float*)d_in[2];
    const float* WQ    = (const float*)d_in[3];
    const float* bQ    = (const float*)d_in[4];
    const float* WK    = (const float*)d_in[5];
    const float* bK    = (const float*)d_in[6];
    const float* WV    = (const float*)d_in[7];
    const float* bV    = (const float*)d_in[8];
    float* out = (float*)d_out;

    k_stats_partial<<<dim3(64, 8), 256>>>(x);
    k_stats_final  <<<16, 256>>>(gamma, beta);
    k_normalize    <<<16384, 256>>>(x);
    k_gemm_qkv     <<<dim3(M_SZ / GBM, 6), 256>>>(WQ, bQ, WK, bK, WV, bV);
    k_attention    <<<B_SZ, 256>>>(x, out);
}